// round 4
// baseline (speedup 1.0000x reference)
#include <cuda_runtime.h>
#include <math.h>

// Problem constants (fixed by reference setup_inputs)
#define B_DIM 32
#define S_DIM 512
#define A_DIM 8
#define L_DIM 32
#define E_DIM 256
#define STILE 32
#define NBLK_X (S_DIM / STILE)          // 16
#define NBLK   (B_DIM * NBLK_X)         // 512
#define TAG_O 1

// Block partial sums: [conf_sum, cls_nll_sum, cls_count, reg_se_sum, pos_count]
__device__ float    g_part[NBLK][5];
__device__ unsigned g_count = 0;

__device__ __forceinline__ float ldcg_f(const float* p) {
    float v;
    asm volatile("ld.global.cg.f32 %0, [%1];" : "=f"(v) : "l"(p));
    return v;
}

__global__ __launch_bounds__(256, 4)
void ssd_loss_fused(const int*   __restrict__ input_len,
                    const float* __restrict__ conf_logits,
                    const float* __restrict__ cls_logits,
                    const float* __restrict__ reg_logits,
                    const float* __restrict__ label,
                    const int*   __restrict__ index,
                    const float* __restrict__ anchors,
                    const float* __restrict__ thr_pos_p,
                    const float* __restrict__ thr_neg_p,
                    float*       __restrict__ out)
{
    const int b    = blockIdx.y;
    const int tile = blockIdx.x;
    const int t    = threadIdx.x;
    const int lane = t & 31;
    const int w    = t >> 5;

    __shared__ float    s_ll[E_DIM];
    __shared__ float    s_lr[E_DIM];
    __shared__ int      s_ty[E_DIM];
    __shared__ int      s_warp_cnt[8];
    __shared__ float    s_red[8][5];
    __shared__ unsigned s_ticket;

    // ---- Anchor assignment + EARLY loads (overlap DRAM latency w/ compaction) ----
    const int s_idx = tile * STILE + (t >> 3);
    const int a     = t & 7;
    const size_t aidx = ((size_t)b * S_DIM + s_idx) * A_DIM + a;

    const float4* row = (const float4*)(cls_logits + aidx * L_DIM);
    float4 q0 = row[0], q1 = row[1], q2 = row[2], q3 = row[3];
    float4 q4 = row[4], q5 = row[5], q6 = row[6], q7 = row[7];
    const float x = conf_logits[aidx];

    const float ac  = anchors[(s_idx * A_DIM + a) * 2 + 0];
    const float asz = anchors[(s_idx * A_DIM + a) * 2 + 1];

    // Row max — cheap fmax tree, consumes load results as they land
    float m;
    {
        float m0 = fmaxf(fmaxf(q0.x, q0.y), fmaxf(q0.z, q0.w));
        float m1 = fmaxf(fmaxf(q1.x, q1.y), fmaxf(q1.z, q1.w));
        float m2 = fmaxf(fmaxf(q2.x, q2.y), fmaxf(q2.z, q2.w));
        float m3 = fmaxf(fmaxf(q3.x, q3.y), fmaxf(q3.z, q3.w));
        float m4 = fmaxf(fmaxf(q4.x, q4.y), fmaxf(q4.z, q4.w));
        float m5 = fmaxf(fmaxf(q5.x, q5.y), fmaxf(q5.z, q5.w));
        float m6 = fmaxf(fmaxf(q6.x, q6.y), fmaxf(q6.z, q6.w));
        float m7 = fmaxf(fmaxf(q7.x, q7.y), fmaxf(q7.z, q7.w));
        m = fmaxf(fmaxf(fmaxf(m0, m1), fmaxf(m2, m3)),
                  fmaxf(fmaxf(m4, m5), fmaxf(m6, m7)));
    }

    // ---- Order-preserving compaction of this batch's entities ----
    {
        const int mine = (index[t] == b) ? 1 : 0;
        const unsigned mask = __ballot_sync(0xffffffffu, mine);
        if (lane == 0) s_warp_cnt[w] = __popc(mask);
        float ty = 0.f, ll = 0.f, lr = 0.f;
        if (mine) {
            ty = label[t * 3 + 0];
            ll = label[t * 3 + 1];
            lr = label[t * 3 + 2];
        }
        __syncthreads();
        int base = 0;
        #pragma unroll
        for (int i = 0; i < 8; i++) if (i < w) base += s_warp_cnt[i];
        if (mine) {
            const int off = base + __popc(mask & ((1u << lane) - 1u));
            s_ty[off] = (int)ty;
            s_ll[off] = ll;
            s_lr[off] = lr;
        }
        __syncthreads();
    }
    int cnt = 0;
    #pragma unroll
    for (int i = 0; i < 8; i++) cnt += s_warp_cnt[i];

    const float al = ac - asz * 0.5f;
    const float ar = ac + asz * 0.5f;
    const float thr_pos = thr_pos_p[0];
    const float thr_neg = thr_neg_p[0];
    const int   len_b   = input_len[b];

    // ---- IOU max / argmax (reference op order, strict > = first-max) ----
    float best = -1.0f;
    int   bk   = 0;
    for (int k = 0; k < cnt; k++) {
        const float ll = s_ll[k];
        const float lr = s_lr[k];
        float inter = fminf(lr, ar) - fmaxf(ll, al);
        inter = fmaxf(inter, 0.0f);
        const float uni = (lr - ll) + (ar - al) - inter;
        const float iou = inter / uni;
        if (iou > best) { best = iou; bk = k; }
    }

    const bool has_ent = (cnt > 0);
    const bool valid   = (s_idx < len_b);
    const bool active  = valid && has_ent;
    const bool pos     = active && (best >= thr_pos);
    const bool neg     = active && (best <= thr_neg);

    // ---- Confidence (BCE-with-logits, mean over ALL anchors) ----
    const float sp = fmaxf(x, 0.0f) + log1pf(expf(-fabsf(x)));
    const float conf_term = sp - (pos ? x : 0.0f);

    // ---- Classification NLL from registers ----
    float cls_nll = 0.0f, cls_c = 0.0f;
    if (pos || neg) {
        const int target = pos ? s_ty[bk] : TAG_O;
        float sum =
            expf(q0.x - m) + expf(q0.y - m) + expf(q0.z - m) + expf(q0.w - m) +
            expf(q1.x - m) + expf(q1.y - m) + expf(q1.z - m) + expf(q1.w - m) +
            expf(q2.x - m) + expf(q2.y - m) + expf(q2.z - m) + expf(q2.w - m) +
            expf(q3.x - m) + expf(q3.y - m) + expf(q3.z - m) + expf(q3.w - m) +
            expf(q4.x - m) + expf(q4.y - m) + expf(q4.z - m) + expf(q4.w - m) +
            expf(q5.x - m) + expf(q5.y - m) + expf(q5.z - m) + expf(q5.w - m) +
            expf(q6.x - m) + expf(q6.y - m) + expf(q6.z - m) + expf(q6.w - m) +
            expf(q7.x - m) + expf(q7.y - m) + expf(q7.z - m) + expf(q7.w - m);

        float tv = q0.x;
        tv = (target ==  1) ? q0.y : tv;  tv = (target ==  2) ? q0.z : tv;  tv = (target ==  3) ? q0.w : tv;
        tv = (target ==  4) ? q1.x : tv;  tv = (target ==  5) ? q1.y : tv;  tv = (target ==  6) ? q1.z : tv;  tv = (target ==  7) ? q1.w : tv;
        tv = (target ==  8) ? q2.x : tv;  tv = (target ==  9) ? q2.y : tv;  tv = (target == 10) ? q2.z : tv;  tv = (target == 11) ? q2.w : tv;
        tv = (target == 12) ? q3.x : tv;  tv = (target == 13) ? q3.y : tv;  tv = (target == 14) ? q3.z : tv;  tv = (target == 15) ? q3.w : tv;
        tv = (target == 16) ? q4.x : tv;  tv = (target == 17) ? q4.y : tv;  tv = (target == 18) ? q4.z : tv;  tv = (target == 19) ? q4.w : tv;
        tv = (target == 20) ? q5.x : tv;  tv = (target == 21) ? q5.y : tv;  tv = (target == 22) ? q5.z : tv;  tv = (target == 23) ? q5.w : tv;
        tv = (target == 24) ? q6.x : tv;  tv = (target == 25) ? q6.y : tv;  tv = (target == 26) ? q6.z : tv;  tv = (target == 27) ? q6.w : tv;
        tv = (target == 28) ? q7.x : tv;  tv = (target == 29) ? q7.y : tv;  tv = (target == 30) ? q7.z : tv;  tv = (target == 31) ? q7.w : tv;

        cls_nll = -(tv - m - logf(sum));
        cls_c   = 1.0f;
    }

    // ---- Regression SE on positives only ----
    float reg_se = 0.0f, pos_c = 0.0f;
    if (pos) {
        const float ll = s_ll[bk];
        const float lr = s_lr[bk];
        const float lc = (ll + lr) * 0.5f;
        const float ls = lr - ll;
        const float oc = (lc - ac) / asz;
        const float os = ls / asz;
        const float r0 = reg_logits[aidx * 2 + 0];
        const float r1 = reg_logits[aidx * 2 + 1];
        reg_se = (r0 - oc) * (r0 - oc) + (r1 - os) * (r1 - os);
        pos_c  = 1.0f;
    }

    // ---- Deterministic block reduction ----
    const int bid = b * NBLK_X + tile;
    {
        float vals[5] = {conf_term, cls_nll, cls_c, reg_se, pos_c};
        #pragma unroll
        for (int j = 0; j < 5; j++) {
            float v = vals[j];
            #pragma unroll
            for (int off = 16; off > 0; off >>= 1)
                v += __shfl_down_sync(0xffffffffu, v, off);
            if (lane == 0) s_red[w][j] = v;
        }
        __syncthreads();
        if (t < 5) {
            float acc = 0.0f;
            #pragma unroll
            for (int i = 0; i < 8; i++) acc += s_red[i][t];
            g_part[bid][t] = acc;
        }
    }

    // ---- Last-block-done final reduction (no second launch) ----
    __threadfence();
    __syncthreads();
    if (t == 0) s_ticket = atomicAdd(&g_count, 1u);
    __syncthreads();
    if (s_ticket != NBLK - 1) return;

    float acc[5];
    #pragma unroll
    for (int j = 0; j < 5; j++)
        acc[j] = ldcg_f(&g_part[t][j]) + ldcg_f(&g_part[t + 256][j]);

    #pragma unroll
    for (int j = 0; j < 5; j++) {
        float v = acc[j];
        #pragma unroll
        for (int off = 16; off > 0; off >>= 1)
            v += __shfl_down_sync(0xffffffffu, v, off);
        if (lane == 0) s_red[w][j] = v;
    }
    __syncthreads();
    if (t == 0) {
        float sums[5];
        #pragma unroll
        for (int j = 0; j < 5; j++) {
            float s = 0.0f;
            #pragma unroll
            for (int i = 0; i < 8; i++) s += s_red[i][j];
            sums[j] = s;
        }
        const float conf_loss = sums[0] / (float)(B_DIM * S_DIM * A_DIM);
        const float cls_loss  = sums[1] / sums[2];
        const float reg_loss  = sums[3] / (sums[4] * 2.0f);
        out[0] = conf_loss + cls_loss + reg_loss;
        out[1] = conf_loss;
        out[2] = cls_loss;
        out[3] = reg_loss;
        atomicExch(&g_count, 0u);   // reset for next graph replay
    }
}

extern "C" void kernel_launch(void* const* d_in, const int* in_sizes, int n_in,
                              void* d_out, int out_size)
{
    const int*   input_len   = (const int*)  d_in[0];
    const float* conf_logits = (const float*)d_in[1];
    const float* cls_logits  = (const float*)d_in[2];
    const float* reg_logits  = (const float*)d_in[3];
    const float* label       = (const float*)d_in[4];
    const int*   index       = (const int*)  d_in[5];
    const float* anchors     = (const float*)d_in[6];
    const float* thr_pos     = (const float*)d_in[7];
    const float* thr_neg     = (const float*)d_in[8];
    float* out = (float*)d_out;

    dim3 grid(NBLK_X, B_DIM);
    ssd_loss_fused<<<grid, 256>>>(input_len, conf_logits, cls_logits, reg_logits,
                                  label, index, anchors, thr_pos, thr_neg, out);
}

// round 6
// speedup vs baseline: 1.1380x; 1.1380x over previous
#include <cuda_runtime.h>
#include <math.h>

// Problem constants (fixed by reference setup_inputs)
#define B_DIM 32
#define S_DIM 512
#define A_DIM 8
#define L_DIM 32
#define E_DIM 256
#define STILE 32
#define NBLK_X (S_DIM / STILE)          // 16
#define NBLK   (B_DIM * NBLK_X)         // 512
#define TAG_O 1

// Block partial sums: [conf_sum, cls_nll_sum, cls_count, reg_se_sum, pos_count]
__device__ float    g_part[NBLK][5];
__device__ unsigned g_count = 0;

__device__ __forceinline__ float ldcg_f(const float* p) {
    float v;
    asm volatile("ld.global.cg.f32 %0, [%1];" : "=f"(v) : "l"(p));
    return v;
}

__global__ __launch_bounds__(256, 4)
void ssd_loss_fused(const int*   __restrict__ input_len,
                    const float* __restrict__ conf_logits,
                    const float* __restrict__ cls_logits,
                    const float* __restrict__ reg_logits,
                    const float* __restrict__ label,
                    const int*   __restrict__ index,
                    const float* __restrict__ anchors,
                    const float* __restrict__ thr_pos_p,
                    const float* __restrict__ thr_neg_p,
                    float*       __restrict__ out)
{
    const int b    = blockIdx.y;
    const int tile = blockIdx.x;
    const int t    = threadIdx.x;
    const int lane = t & 31;
    const int w    = t >> 5;

    __shared__ float    s_ll[E_DIM];
    __shared__ float    s_lr[E_DIM];
    __shared__ int      s_ty[E_DIM];
    __shared__ int      s_warp_cnt[8];
    __shared__ float    s_red[8][5];
    __shared__ unsigned s_ticket;

    // ---- Anchor assignment (light loads only — no front-batched LDG burst) ----
    const int s_idx = tile * STILE + (t >> 3);
    const int a     = t & 7;
    const size_t aidx = ((size_t)b * S_DIM + s_idx) * A_DIM + a;

    const float x   = conf_logits[aidx];
    const float ac  = anchors[(s_idx * A_DIM + a) * 2 + 0];
    const float asz = anchors[(s_idx * A_DIM + a) * 2 + 1];

    // ---- Order-preserving compaction of this batch's entities ----
    {
        const int mine = (index[t] == b) ? 1 : 0;
        const unsigned mask = __ballot_sync(0xffffffffu, mine);
        if (lane == 0) s_warp_cnt[w] = __popc(mask);
        float ty = 0.f, ll = 0.f, lr = 0.f;
        if (mine) {
            ty = label[t * 3 + 0];
            ll = label[t * 3 + 1];
            lr = label[t * 3 + 2];
        }
        __syncthreads();
        int base = 0;
        #pragma unroll
        for (int i = 0; i < 8; i++) if (i < w) base += s_warp_cnt[i];
        if (mine) {
            const int off = base + __popc(mask & ((1u << lane) - 1u));
            s_ty[off] = (int)ty;
            s_ll[off] = ll;
            s_lr[off] = lr;
        }
        __syncthreads();
    }
    int cnt = 0;
    #pragma unroll
    for (int i = 0; i < 8; i++) cnt += s_warp_cnt[i];

    const float al = ac - asz * 0.5f;
    const float ar = ac + asz * 0.5f;
    const float thr_pos = thr_pos_p[0];
    const float thr_neg = thr_neg_p[0];
    const int   len_b   = input_len[b];

    // ---- IOU max / argmax (reference op order, strict > = first-max) ----
    float best = -1.0f;
    int   bk   = 0;
    for (int k = 0; k < cnt; k++) {
        const float ll = s_ll[k];
        const float lr = s_lr[k];
        float inter = fminf(lr, ar) - fmaxf(ll, al);
        inter = fmaxf(inter, 0.0f);
        const float uni = (lr - ll) + (ar - al) - inter;
        const float iou = inter / uni;
        if (iou > best) { best = iou; bk = k; }
    }

    const bool has_ent = (cnt > 0);
    const bool valid   = (s_idx < len_b);
    const bool active  = valid && has_ent;
    const bool pos     = active && (best >= thr_pos);
    const bool neg     = active && (best <= thr_neg);

    // ---- Confidence (BCE-with-logits, mean over ALL anchors) ----
    const float sp = fmaxf(x, 0.0f) + __logf(1.0f + __expf(-fabsf(x)));
    const float conf_term = sp - (pos ? x : 0.0f);

    // ---- Classification NLL: load row ONLY where needed (~75% of anchors) ----
    float cls_nll = 0.0f, cls_c = 0.0f;
    if (pos || neg) {
        const int target = pos ? s_ty[bk] : TAG_O;
        const float* rowf = cls_logits + aidx * L_DIM;
        const float tv = rowf[target];               // scalar load, issued first
        const float4* row = (const float4*)rowf;
        const float4 q0 = row[0], q1 = row[1], q2 = row[2], q3 = row[3];
        const float4 q4 = row[4], q5 = row[5], q6 = row[6], q7 = row[7];

        float m0 = fmaxf(fmaxf(q0.x, q0.y), fmaxf(q0.z, q0.w));
        float m1 = fmaxf(fmaxf(q1.x, q1.y), fmaxf(q1.z, q1.w));
        float m2 = fmaxf(fmaxf(q2.x, q2.y), fmaxf(q2.z, q2.w));
        float m3 = fmaxf(fmaxf(q3.x, q3.y), fmaxf(q3.z, q3.w));
        float m4 = fmaxf(fmaxf(q4.x, q4.y), fmaxf(q4.z, q4.w));
        float m5 = fmaxf(fmaxf(q5.x, q5.y), fmaxf(q5.z, q5.w));
        float m6 = fmaxf(fmaxf(q6.x, q6.y), fmaxf(q6.z, q6.w));
        float m7 = fmaxf(fmaxf(q7.x, q7.y), fmaxf(q7.z, q7.w));
        const float m = fmaxf(fmaxf(fmaxf(m0, m1), fmaxf(m2, m3)),
                              fmaxf(fmaxf(m4, m5), fmaxf(m6, m7)));

        float sum =
            __expf(q0.x - m) + __expf(q0.y - m) + __expf(q0.z - m) + __expf(q0.w - m) +
            __expf(q1.x - m) + __expf(q1.y - m) + __expf(q1.z - m) + __expf(q1.w - m) +
            __expf(q2.x - m) + __expf(q2.y - m) + __expf(q2.z - m) + __expf(q2.w - m) +
            __expf(q3.x - m) + __expf(q3.y - m) + __expf(q3.z - m) + __expf(q3.w - m) +
            __expf(q4.x - m) + __expf(q4.y - m) + __expf(q4.z - m) + __expf(q4.w - m) +
            __expf(q5.x - m) + __expf(q5.y - m) + __expf(q5.z - m) + __expf(q5.w - m) +
            __expf(q6.x - m) + __expf(q6.y - m) + __expf(q6.z - m) + __expf(q6.w - m) +
            __expf(q7.x - m) + __expf(q7.y - m) + __expf(q7.z - m) + __expf(q7.w - m);

        cls_nll = -(tv - m - __logf(sum));
        cls_c   = 1.0f;
    }

    // ---- Regression SE on positives only ----
    float reg_se = 0.0f, pos_c = 0.0f;
    if (pos) {
        const float ll = s_ll[bk];
        const float lr = s_lr[bk];
        const float lc = (ll + lr) * 0.5f;
        const float ls = lr - ll;
        const float oc = (lc - ac) / asz;
        const float os = ls / asz;
        const float r0 = reg_logits[aidx * 2 + 0];
        const float r1 = reg_logits[aidx * 2 + 1];
        reg_se = (r0 - oc) * (r0 - oc) + (r1 - os) * (r1 - os);
        pos_c  = 1.0f;
    }

    // ---- Deterministic block reduction ----
    const int bid = b * NBLK_X + tile;
    {
        float vals[5] = {conf_term, cls_nll, cls_c, reg_se, pos_c};
        #pragma unroll
        for (int j = 0; j < 5; j++) {
            float v = vals[j];
            #pragma unroll
            for (int off = 16; off > 0; off >>= 1)
                v += __shfl_down_sync(0xffffffffu, v, off);
            if (lane == 0) s_red[w][j] = v;
        }
        __syncthreads();
        if (t < 5) {
            float acc = 0.0f;
            #pragma unroll
            for (int i = 0; i < 8; i++) acc += s_red[i][t];
            g_part[bid][t] = acc;
        }
    }

    // ---- Last-block-done final reduction (no second launch) ----
    __threadfence();
    __syncthreads();
    if (t == 0) s_ticket = atomicAdd(&g_count, 1u);
    __syncthreads();
    if (s_ticket != NBLK - 1) return;

    float acc[5];
    #pragma unroll
    for (int j = 0; j < 5; j++)
        acc[j] = ldcg_f(&g_part[t][j]) + ldcg_f(&g_part[t + 256][j]);

    #pragma unroll
    for (int j = 0; j < 5; j++) {
        float v = acc[j];
        #pragma unroll
        for (int off = 16; off > 0; off >>= 1)
            v += __shfl_down_sync(0xffffffffu, v, off);
        if (lane == 0) s_red[w][j] = v;
    }
    __syncthreads();
    if (t == 0) {
        float sums[5];
        #pragma unroll
        for (int j = 0; j < 5; j++) {
            float s = 0.0f;
            #pragma unroll
            for (int i = 0; i < 8; i++) s += s_red[i][j];
            sums[j] = s;
        }
        const float conf_loss = sums[0] / (float)(B_DIM * S_DIM * A_DIM);
        const float cls_loss  = sums[1] / sums[2];
        const float reg_loss  = sums[3] / (sums[4] * 2.0f);
        out[0] = conf_loss + cls_loss + reg_loss;
        out[1] = conf_loss;
        out[2] = cls_loss;
        out[3] = reg_loss;
        atomicExch(&g_count, 0u);   // reset for next graph replay
    }
}

extern "C" void kernel_launch(void* const* d_in, const int* in_sizes, int n_in,
                              void* d_out, int out_size)
{
    const int*   input_len   = (const int*)  d_in[0];
    const float* conf_logits = (const float*)d_in[1];
    const float* cls_logits  = (const float*)d_in[2];
    const float* reg_logits  = (const float*)d_in[3];
    const float* label       = (const float*)d_in[4];
    const int*   index       = (const int*)  d_in[5];
    const float* anchors     = (const float*)d_in[6];
    const float* thr_pos     = (const float*)d_in[7];
    const float* thr_neg     = (const float*)d_in[8];
    float* out = (float*)d_out;

    dim3 grid(NBLK_X, B_DIM);
    ssd_loss_fused<<<grid, 256>>>(input_len, conf_logits, cls_logits, reg_logits,
                                  label, index, anchors, thr_pos, thr_neg, out);
}